// round 14
// baseline (speedup 1.0000x reference)
#include <cuda_runtime.h>
#include <cuda_fp16.h>
#include <math.h>
#include <stdint.h>

#define NIMG  256
#define PLANE 65536
#define TOT   16777216

// Scratch (__device__ globals per allocation rules)
__device__ uint32_t g_AB[TOT];         // packed half2 (a, b) per element
__device__ uint32_t g_O1p[TOT/2];      // layer1 output, channel-pair half2 packed
__device__ float    g_hdump[4*PLANE];
__device__ uint32_t g_U1[32768];       // Winograd-transformed weights, fragment order
__device__ uint32_t g_U2[65536];

__device__ __forceinline__ float sigm(float x) { return 1.f/(1.f+__expf(-x)); }
__device__ __forceinline__ uint32_t pkh2(float a, float b) {
    __half2 h = __floats2half2_rn(a, b);
    return *(uint32_t*)&h;
}
__device__ __forceinline__ uint32_t smem_u32(const void* p) {
    uint32_t a;
    asm("{ .reg .u64 t; cvta.to.shared.u64 t, %1; cvt.u32.u64 %0, t; }" : "=r"(a) : "l"(p));
    return a;
}
#define CP_ASYNC16(dst, src) \
    asm volatile("cp.async.cg.shared.global [%0], [%1], 16;" :: "r"(dst), "l"(src) : "memory")
#define CP_COMMIT()  asm volatile("cp.async.commit_group;" ::: "memory")
#define CP_WAIT(n)   asm volatile("cp.async.wait_group %0;" :: "n"(n) : "memory")

// Pack Winograd-transformed weights U = G w G^T (4x4 per oc,ic) into mma-fragment
// order: slab = (p*4 + ocgrp)*2 + f ; per slab KC chunks of 128 u32 (lane*4 + q).
template<int IC>
__device__ __forceinline__ void pack_u_body(const float* __restrict__ w,
                                            uint32_t* __restrict__ dst, int idx) {
    constexpr int KC = IC / 16;
    if (idx >= 128 * KC * 128) return;
    int slab = idx / (KC * 128);
    int rem  = idx - slab * (KC * 128);
    int c = rem >> 7, rem2 = rem & 127;
    int lane = rem2 >> 2, q = rem2 & 3;
    int f  = slab & 1;
    int og = (slab >> 1) & 3;
    int p  = slab >> 3;
    int xi = p >> 2, eta = p & 3;
    int oc = f * 64 + og * 16 + (lane >> 2) + (q & 1) * 8;
    int k  = c * 16 + 2 * (lane & 3) + (q >> 1) * 8;
    const float G[4][3] = {{1,0,0},{0.5f,0.5f,0.5f},{0.5f,-0.5f,0.5f},{0,0,1}};
    float u[2];
    #pragma unroll
    for (int t = 0; t < 2; t++) {
        const float* wp = w + (oc * IC + k + t) * 9;
        float a = 0.f;
        for (int i = 0; i < 3; i++)
            for (int j = 0; j < 3; j++)
                a += G[xi][i] * G[eta][j] * wp[i * 3 + j];
        u[t] = a;
    }
    dst[idx] = pkh2(u[0], u[1]);
}

// Single launch packs both layers: blocks [0,128) -> U1 (IC=32), [128,384) -> U2.
__global__ void __launch_bounds__(256)
pack_both(const float* __restrict__ w1, uint32_t* __restrict__ d1,
          const float* __restrict__ w2, uint32_t* __restrict__ d2) {
    int bx = blockIdx.x;
    if (bx < 128) pack_u_body<32>(w1, d1, bx * 256 + threadIdx.x);
    else          pack_u_body<64>(w2, d2, (bx - 128) * 256 + threadIdx.x);
}

// Winograd F(2x2,3x3) conv + fused minGRU epilogue. R12 tiling; NEW: per-point U
// slab is cp.async double-buffered into smem (reusing the dead tile2 region), so
// mainloop A-fragments are conflict-free LDS.128 instead of 4x-redundant LDG.
template<int IC, bool PIN>
__global__ void __launch_bounds__(512, 1)
conv_wino(const void* __restrict__ xin_, const uint32_t* __restrict__ Upk,
          const float* __restrict__ bias, uint32_t* __restrict__ ABout)
{
    extern __shared__ uint32_t sm[];
    constexpr int KC   = IC / 16;
    constexpr int ICP  = IC / 2;
    constexpr int VP   = ICP * 72;         // u32 per transform point
    constexpr int PBLK = KC * 1024;        // u32 per p-block of U (4 og x 2 f x KC*128)
    uint32_t* tile2 = sm;                  // [ICP][10 rows][36 cols] half2 (dead after transform)
    uint32_t* V     = sm + ICP * 360;      // [16 points][ICP kpairs][72 (64 tiles)]
    uint32_t* Ubuf  = sm;                  // overlay: 2 x PBLK u32 U stage (fits: 2*PBLK <= ICP*360)

    const int tid = threadIdx.x;
    const int wv = tid >> 5, lane = tid & 31;
    const int g4 = lane >> 2, tig = lane & 3;
    const int og = wv & 3, tg = wv >> 2;
    const int blk = blockIdx.x, band = blk & 3, n = blk >> 2, r0 = band * 8;

    // Stage padded input: rows r0-1..r0+8 (10), cols -1..33 (36), channel-pair half2
    for (int idx = tid; idx < ICP * 360; idx += 512) {
        int icp = idx / 360, rem = idx - icp * 360, r = rem / 36, c = rem - r * 36;
        int gr = r0 + r - 1, gc = c - 1;
        uint32_t v = 0;
        if ((unsigned)gr < 32u && (unsigned)gc < 32u) {
            if (PIN) {
                v = ((const uint32_t*)xin_)[n * 32768 + icp * 1024 + (gr << 5) + gc];
            } else {
                const float* x = (const float*)xin_;
                int base = ((n * IC + 2 * icp) << 10) + (gr << 5) + gc;
                v = pkh2(x[base], x[base + 1024]);
            }
        }
        tile2[idx] = v;
    }
    __syncthreads();

    // Input transform: per (icpair, tile): V = B^T d B (on half2 = 2 channels at once)
    for (int u = tid; u < ICP * 64; u += 512) {
        int icp = u >> 6, rem = u & 63, tr = rem >> 4, tc = rem & 15;
        const uint32_t* dp = tile2 + icp * 360 + (2 * tr) * 36 + 2 * tc;
        float2 d[4][4];
        #pragma unroll
        for (int i = 0; i < 4; i++)
            #pragma unroll
            for (int j = 0; j < 4; j++) {
                uint32_t raw = dp[i * 36 + j];
                d[i][j] = __half22float2(*(__half2*)&raw);
            }
        float2 t[4][4];
        #pragma unroll
        for (int j = 0; j < 4; j++) {
            t[0][j] = make_float2(d[0][j].x - d[2][j].x, d[0][j].y - d[2][j].y);
            t[1][j] = make_float2(d[1][j].x + d[2][j].x, d[1][j].y + d[2][j].y);
            t[2][j] = make_float2(d[2][j].x - d[1][j].x, d[2][j].y - d[1][j].y);
            t[3][j] = make_float2(d[1][j].x - d[3][j].x, d[1][j].y - d[3][j].y);
        }
        uint32_t* vp = V + icp * 72 + tr * 16 + tc;
        #pragma unroll
        for (int xi = 0; xi < 4; xi++) {
            float2 v0 = make_float2(t[xi][0].x - t[xi][2].x, t[xi][0].y - t[xi][2].y);
            float2 v1 = make_float2(t[xi][1].x + t[xi][2].x, t[xi][1].y + t[xi][2].y);
            float2 v2 = make_float2(t[xi][2].x - t[xi][1].x, t[xi][2].y - t[xi][1].y);
            float2 v3 = make_float2(t[xi][1].x - t[xi][3].x, t[xi][1].y - t[xi][3].y);
            vp[(xi * 4 + 0) * VP] = pkh2(v0.x, v0.y);
            vp[(xi * 4 + 1) * VP] = pkh2(v1.x, v1.y);
            vp[(xi * 4 + 2) * VP] = pkh2(v2.x, v2.y);
            vp[(xi * 4 + 3) * VP] = pkh2(v3.x, v3.y);
        }
    }
    __syncthreads();   // tile2 dead from here; Ubuf overlay becomes live

    const uint32_t ub_base = smem_u32(Ubuf);

    // Stage U p-block via cp.async: PBLK u32 = PBLK/4 16B chunks, 512 threads
    auto stage_u = [&](int p, int buf) {
        const uint32_t* src = Upk + p * PBLK;
        uint32_t dstb = ub_base + buf * (PBLK * 4);
        #pragma unroll
        for (int i = 0; i < PBLK / 2048; i++) {
            int e = tid + i * 512;
            CP_ASYNC16(dstb + e * 16, src + e * 4);
        }
    };

    stage_u(0, 0);
    CP_COMMIT();

    float Y[2][2][4][4];   // [f gate/hid][nf][acc j][di*2+dj]
    #pragma unroll
    for (int f = 0; f < 2; f++)
        #pragma unroll
        for (int nf = 0; nf < 2; nf++)
            #pragma unroll
            for (int j = 0; j < 4; j++)
                #pragma unroll
                for (int e = 0; e < 4; e++) Y[f][nf][j][e] = 0.f;

    for (int p = 0; p < 16; p++) {
        if (p < 15) { stage_u(p + 1, (p + 1) & 1); CP_COMMIT(); CP_WAIT(1); }
        else        { CP_WAIT(0); }
        __syncthreads();   // buf p&1 filled; all warps done with the buffer being overwritten

        float M[2][2][4];
        #pragma unroll
        for (int f = 0; f < 2; f++)
            #pragma unroll
            for (int nf = 0; nf < 2; nf++)
                #pragma unroll
                for (int j = 0; j < 4; j++) M[f][nf][j] = 0.f;

        const uint32_t* Ub = Ubuf + (p & 1) * PBLK + (og * 2) * (KC * 128);
        const uint32_t* Vb = V + p * VP + tig * 72 + tg * 16 + g4;
        #pragma unroll
        for (int c = 0; c < KC; c++) {
            uint4 a0 = *(const uint4*)(Ub + c * 128 + lane * 4);
            uint4 a1 = *(const uint4*)(Ub + KC * 128 + c * 128 + lane * 4);
            uint32_t b00 = Vb[(c * 8) * 72];
            uint32_t b01 = Vb[(c * 8 + 4) * 72];
            uint32_t b10 = Vb[(c * 8) * 72 + 8];
            uint32_t b11 = Vb[(c * 8 + 4) * 72 + 8];
            #pragma unroll
            for (int f = 0; f < 2; f++) {
                uint4 aa = f ? a1 : a0;
                asm volatile(
                    "mma.sync.aligned.m16n8k16.row.col.f32.f16.f16.f32 "
                    "{%0,%1,%2,%3}, {%4,%5,%6,%7}, {%8,%9}, {%0,%1,%2,%3};"
                    : "+f"(M[f][0][0]), "+f"(M[f][0][1]), "+f"(M[f][0][2]), "+f"(M[f][0][3])
                    : "r"(aa.x), "r"(aa.y), "r"(aa.z), "r"(aa.w), "r"(b00), "r"(b01));
                asm volatile(
                    "mma.sync.aligned.m16n8k16.row.col.f32.f16.f16.f32 "
                    "{%0,%1,%2,%3}, {%4,%5,%6,%7}, {%8,%9}, {%0,%1,%2,%3};"
                    : "+f"(M[f][1][0]), "+f"(M[f][1][1]), "+f"(M[f][1][2]), "+f"(M[f][1][3])
                    : "r"(aa.x), "r"(aa.y), "r"(aa.z), "r"(aa.w), "r"(b10), "r"(b11));
            }
        }
        // Fold M into Y with A^T coeffs: At0 = [1,1,1,0], At1 = [0,1,-1,-1]
        int xi = p >> 2, eta = p & 3;
        float cx0 = (xi == 3) ? 0.f : 1.f;
        float cx1 = (xi == 0) ? 0.f : ((xi == 1) ? 1.f : -1.f);
        float cy0 = (eta == 3) ? 0.f : 1.f;
        float cy1 = (eta == 0) ? 0.f : ((eta == 1) ? 1.f : -1.f);
        float c00 = cx0 * cy0, c01 = cx0 * cy1, c10 = cx1 * cy0, c11 = cx1 * cy1;
        #pragma unroll
        for (int f = 0; f < 2; f++)
            #pragma unroll
            for (int nf = 0; nf < 2; nf++)
                #pragma unroll
                for (int j = 0; j < 4; j++) {
                    float m = M[f][nf][j];
                    Y[f][nf][j][0] = fmaf(c00, m, Y[f][nf][j][0]);
                    Y[f][nf][j][1] = fmaf(c01, m, Y[f][nf][j][1]);
                    Y[f][nf][j][2] = fmaf(c10, m, Y[f][nf][j][2]);
                    Y[f][nf][j][3] = fmaf(c11, m, Y[f][nf][j][3]);
                }
        __syncthreads();   // all warps done reading buf p&1 before it is restaged
    }

    // Fused minGRU epilogue -> packed half2 (a, b), uint2 per 2x1 px pair
    const float bg0 = __ldg(bias + og * 16 + g4),      bg1 = __ldg(bias + og * 16 + g4 + 8);
    const float bh0 = __ldg(bias + 64 + og * 16 + g4), bh1 = __ldg(bias + 64 + og * 16 + g4 + 8);
    #pragma unroll
    for (int nf = 0; nf < 2; nf++)
        #pragma unroll
        for (int j = 0; j < 4; j++) {
            int oc = og * 16 + g4 + ((j >> 1) * 8);
            int tc = nf * 8 + 2 * tig + (j & 1);
            float bg = (j >> 1) ? bg1 : bg0, bh = (j >> 1) ? bh1 : bh0;
            #pragma unroll
            for (int di = 0; di < 2; di++) {
                int row = r0 + 2 * tg + di;
                float g0 = Y[0][nf][j][di * 2 + 0] + bg;
                float g1 = Y[0][nf][j][di * 2 + 1] + bg;
                float h0 = Y[1][nf][j][di * 2 + 0] + bh;
                float h1 = Y[1][nf][j][di * 2 + 1] + bh;
                float z0 = sigm(g0), z1 = sigm(g1);
                float q0 = (h0 >= 0.f) ? h0 + 0.5f : sigm(h0);
                float q1 = (h1 >= 0.f) ? h1 + 0.5f : sigm(h1);
                uint2 pk;
                pk.x = pkh2(1.f - z0, z0 * q0);
                pk.y = pkh2(1.f - z1, z1 * q1);
                *(uint2*)(ABout + ((n * 64 + oc) << 10) + (row << 5) + 2 * tc) = pk;
            }
        }
}

// Scan layer 1 (R12-verified): one thread per channel PAIR; reads packed (a,b);
// writes packed half2 O1 + fp32 h1.
__global__ void __launch_bounds__(256)
scan1_k(const uint32_t* __restrict__ AB,
        uint32_t* __restrict__ o1p, float* __restrict__ h1)
{
    int idx = blockIdx.x * 256 + threadIdx.x;       // 131072
    int b = idx >> 15, rem = idx & 32767;
    int icp = rem >> 10, px = rem & 1023;
    size_t base = (size_t)b * 64 * 65536 + icp * 2048 + px;
    float h0 = 0.5f, h1v = 0.5f;
    #pragma unroll 8
    for (int t = 0; t < 64; t++) {
        size_t off = base + (size_t)t * 65536;
        uint32_t p0 = AB[off], p1 = AB[off + 1024];
        float2 c0 = __half22float2(*(__half2*)&p0);
        float2 c1 = __half22float2(*(__half2*)&p1);
        h0  = fmaf(c0.x, h0,  c0.y);
        h1v = fmaf(c1.x, h1v, c1.y);
        o1p[(size_t)(b * 64 + t) * 32768 + rem] = pkh2(h0, h1v);
    }
    h1[b * 65536 + icp * 2048 + px]        = h0;
    h1[b * 65536 + icp * 2048 + 1024 + px] = h1v;
}

// Scan layer 2 (R12-verified): reads packed (a,b); fp32 out, float2 stores.
__global__ void __launch_bounds__(256)
scan2_k(const uint32_t* __restrict__ AB,
        float* __restrict__ out, float* __restrict__ h2)
{
    int idx = blockIdx.x * 256 + threadIdx.x;       // 131072 px-pair lanes
    int b = idx >> 15, j = idx & 32767;
    size_t base = (size_t)b * 64 * 32768 + j;
    const uint2* AB2 = (const uint2*)AB;
    float2* o2 = (float2*)out;
    float h0 = 0.5f, h1v = 0.5f;
    #pragma unroll 8
    for (int t = 0; t < 64; t++) {
        size_t off = base + (size_t)t * 32768;
        uint2 p = AB2[off];
        float2 c0 = __half22float2(*(__half2*)&p.x);
        float2 c1 = __half22float2(*(__half2*)&p.y);
        h0  = fmaf(c0.x, h0,  c0.y);
        h1v = fmaf(c1.x, h1v, c1.y);
        o2[off] = make_float2(h0, h1v);
    }
    ((float2*)h2)[b * 32768 + j] = make_float2(h0, h1v);
}

extern "C" void kernel_launch(void* const* d_in, const int* in_sizes, int n_in,
                              void* d_out, int out_size) {
    const float* x  = (const float*)d_in[0];
    const float* w1 = (const float*)d_in[1];
    const float* b1 = (const float*)d_in[2];
    const float* w2 = (const float*)d_in[3];
    const float* b2 = (const float*)d_in[4];
    float* out = (float*)d_out;

    float *pH;
    uint32_t *pAB, *pO1p, *pU1, *pU2;
    cudaGetSymbolAddress((void**)&pAB,  g_AB);
    cudaGetSymbolAddress((void**)&pO1p, g_O1p);
    cudaGetSymbolAddress((void**)&pH,   g_hdump);
    cudaGetSymbolAddress((void**)&pU1,  g_U1);
    cudaGetSymbolAddress((void**)&pU2,  g_U2);

    const int SMEM1 = (16 * 360 + 16 * 16 * 72) * 4;   //  96768
    const int SMEM2 = (32 * 360 + 16 * 32 * 72) * 4;   // 193536
    cudaFuncSetAttribute(conv_wino<32,false>, cudaFuncAttributeMaxDynamicSharedMemorySize, SMEM1);
    cudaFuncSetAttribute(conv_wino<64,true>,  cudaFuncAttributeMaxDynamicSharedMemorySize, SMEM2);

    bool full = (out_size >= TOT + 8 * PLANE);
    float* h1 = full ? (out + TOT)             : pH;
    float* h2 = full ? (out + TOT + 4 * PLANE) : pH;

    pack_both<<<384, 256>>>(w1, pU1, w2, pU2);
    conv_wino<32,false><<<1024, 512, SMEM1>>>(x, pU1, b1, pAB);
    scan1_k<<<512, 256>>>(pAB, pO1p, h1);
    conv_wino<64,true><<<1024, 512, SMEM2>>>(pO1p, pU2, b2, pAB);
    scan2_k<<<512, 256>>>(pAB, out, h2);
}

// round 15
// speedup vs baseline: 1.0859x; 1.0859x over previous
#include <cuda_runtime.h>
#include <cuda_fp16.h>
#include <math.h>
#include <stdint.h>

#define NIMG  256
#define PLANE 65536
#define TOT   16777216

// Scratch (__device__ globals per allocation rules)
__device__ uint32_t g_AB[TOT];         // packed half2 (a, b) per element
__device__ uint32_t g_O1p[TOT/2];      // layer1 output, channel-pair half2 packed
__device__ float    g_hdump[4*PLANE];
__device__ uint32_t g_U1[32768];       // Winograd-transformed weights, fragment order
__device__ uint32_t g_U2[65536];

__device__ __forceinline__ float sigm(float x) { return 1.f/(1.f+__expf(-x)); }
__device__ __forceinline__ uint32_t pkh2(float a, float b) {
    __half2 h = __floats2half2_rn(a, b);
    return *(uint32_t*)&h;
}

// Pack Winograd-transformed weights U = G w G^T (4x4 per oc,ic) into mma-fragment
// order: slab = (p*4 + ocgrp)*2 + f ; per slab KC chunks of 128 u32 (lane*4 + q).
template<int IC>
__device__ __forceinline__ void pack_u_body(const float* __restrict__ w,
                                            uint32_t* __restrict__ dst, int idx) {
    constexpr int KC = IC / 16;
    if (idx >= 128 * KC * 128) return;
    int slab = idx / (KC * 128);
    int rem  = idx - slab * (KC * 128);
    int c = rem >> 7, rem2 = rem & 127;
    int lane = rem2 >> 2, q = rem2 & 3;
    int f  = slab & 1;
    int og = (slab >> 1) & 3;
    int p  = slab >> 3;
    int xi = p >> 2, eta = p & 3;
    int oc = f * 64 + og * 16 + (lane >> 2) + (q & 1) * 8;
    int k  = c * 16 + 2 * (lane & 3) + (q >> 1) * 8;
    const float G[4][3] = {{1,0,0},{0.5f,0.5f,0.5f},{0.5f,-0.5f,0.5f},{0,0,1}};
    float u[2];
    #pragma unroll
    for (int t = 0; t < 2; t++) {
        const float* wp = w + (oc * IC + k + t) * 9;
        float a = 0.f;
        for (int i = 0; i < 3; i++)
            for (int j = 0; j < 3; j++)
                a += G[xi][i] * G[eta][j] * wp[i * 3 + j];
        u[t] = a;
    }
    dst[idx] = pkh2(u[0], u[1]);
}

// Single launch packs both layers: blocks [0,128) -> U1 (IC=32), [128,384) -> U2.
__global__ void __launch_bounds__(256)
pack_both(const float* __restrict__ w1, uint32_t* __restrict__ d1,
          const float* __restrict__ w2, uint32_t* __restrict__ d2) {
    int bx = blockIdx.x;
    if (bx < 128) pack_u_body<32>(w1, d1, bx * 256 + threadIdx.x);
    else          pack_u_body<64>(w2, d2, (bx - 128) * 256 + threadIdx.x);
}

// Winograd F(2x2,3x3) conv + fused minGRU epilogue. R12 structure verbatim,
// EXCEPT: V tiles within each 16-tile row-group stored interleaved
// (pos = (t&7)*2 + t>>3) so the mainloop's tile pair (g4, g4+8) is adjacent
// -> one LDS.64 per B-fragment pair (256 -> 128 V loads/thread). Values,
// arithmetic and order identical; bank-conflict-free both sides (verified).
template<int IC, bool PIN>
__global__ void __launch_bounds__(512, 1)
conv_wino(const void* __restrict__ xin_, const uint32_t* __restrict__ Upk,
          const float* __restrict__ bias, uint32_t* __restrict__ ABout)
{
    extern __shared__ uint32_t sm[];
    constexpr int KC  = IC / 16;
    constexpr int ICP = IC / 2;
    constexpr int VP  = ICP * 72;          // u32 per transform point
    uint32_t* tile2 = sm;                  // [ICP][10 rows][36 cols] half2
    uint32_t* V     = sm + ICP * 360;      // [16 points][ICP kpairs][72 (64 tiles)]

    const int tid = threadIdx.x;
    const int wv = tid >> 5, lane = tid & 31;
    const int g4 = lane >> 2, tig = lane & 3;
    const int og = wv & 3, tg = wv >> 2;
    const int blk = blockIdx.x, band = blk & 3, n = blk >> 2, r0 = band * 8;

    // Stage padded input: rows r0-1..r0+8 (10), cols -1..33 (36), channel-pair half2
    for (int idx = tid; idx < ICP * 360; idx += 512) {
        int icp = idx / 360, rem = idx - icp * 360, r = rem / 36, c = rem - r * 36;
        int gr = r0 + r - 1, gc = c - 1;
        uint32_t v = 0;
        if ((unsigned)gr < 32u && (unsigned)gc < 32u) {
            if (PIN) {
                v = ((const uint32_t*)xin_)[n * 32768 + icp * 1024 + (gr << 5) + gc];
            } else {
                const float* x = (const float*)xin_;
                int base = ((n * IC + 2 * icp) << 10) + (gr << 5) + gc;
                v = pkh2(x[base], x[base + 1024]);
            }
        }
        tile2[idx] = v;
    }
    __syncthreads();

    // Input transform: per (icpair, tile): V = B^T d B (on half2 = 2 channels at once)
    // Tile stored at interleaved position (tc&7)*2 + (tc>>3) within its row-group.
    for (int u = tid; u < ICP * 64; u += 512) {
        int icp = u >> 6, rem = u & 63, tr = rem >> 4, tc = rem & 15;
        const uint32_t* dp = tile2 + icp * 360 + (2 * tr) * 36 + 2 * tc;
        float2 d[4][4];
        #pragma unroll
        for (int i = 0; i < 4; i++)
            #pragma unroll
            for (int j = 0; j < 4; j++) {
                uint32_t raw = dp[i * 36 + j];
                d[i][j] = __half22float2(*(__half2*)&raw);
            }
        float2 t[4][4];
        #pragma unroll
        for (int j = 0; j < 4; j++) {
            t[0][j] = make_float2(d[0][j].x - d[2][j].x, d[0][j].y - d[2][j].y);
            t[1][j] = make_float2(d[1][j].x + d[2][j].x, d[1][j].y + d[2][j].y);
            t[2][j] = make_float2(d[2][j].x - d[1][j].x, d[2][j].y - d[1][j].y);
            t[3][j] = make_float2(d[1][j].x - d[3][j].x, d[1][j].y - d[3][j].y);
        }
        uint32_t* vp = V + icp * 72 + tr * 16 + ((tc & 7) * 2 + (tc >> 3));
        #pragma unroll
        for (int xi = 0; xi < 4; xi++) {
            float2 v0 = make_float2(t[xi][0].x - t[xi][2].x, t[xi][0].y - t[xi][2].y);
            float2 v1 = make_float2(t[xi][1].x + t[xi][2].x, t[xi][1].y + t[xi][2].y);
            float2 v2 = make_float2(t[xi][2].x - t[xi][1].x, t[xi][2].y - t[xi][1].y);
            float2 v3 = make_float2(t[xi][1].x - t[xi][3].x, t[xi][1].y - t[xi][3].y);
            vp[(xi * 4 + 0) * VP] = pkh2(v0.x, v0.y);
            vp[(xi * 4 + 1) * VP] = pkh2(v1.x, v1.y);
            vp[(xi * 4 + 2) * VP] = pkh2(v2.x, v2.y);
            vp[(xi * 4 + 3) * VP] = pkh2(v3.x, v3.y);
        }
    }
    __syncthreads();

    float Y[2][2][4][4];   // [f gate/hid][nf][acc j][di*2+dj]
    #pragma unroll
    for (int f = 0; f < 2; f++)
        #pragma unroll
        for (int nf = 0; nf < 2; nf++)
            #pragma unroll
            for (int j = 0; j < 4; j++)
                #pragma unroll
                for (int e = 0; e < 4; e++) Y[f][nf][j][e] = 0.f;

    for (int p = 0; p < 16; p++) {
        float M[2][2][4];
        #pragma unroll
        for (int f = 0; f < 2; f++)
            #pragma unroll
            for (int nf = 0; nf < 2; nf++)
                #pragma unroll
                for (int j = 0; j < 4; j++) M[f][nf][j] = 0.f;

        const uint32_t* Ub = Upk + (size_t)((p * 4 + og) * 2) * KC * 128;
        // Interleaved layout: tiles (tg*16+g4) and (tg*16+g4+8) are adjacent u32s.
        const uint32_t* Vb = V + p * VP + tig * 72 + tg * 16 + 2 * g4;
        #pragma unroll
        for (int c = 0; c < KC; c++) {
            uint4 a0 = *(const uint4*)(Ub + c * 128 + lane * 4);
            uint4 a1 = *(const uint4*)(Ub + KC * 128 + c * 128 + lane * 4);
            uint2 B0 = *(const uint2*)(Vb + (c * 8) * 72);       // {b00, b10}
            uint2 B1 = *(const uint2*)(Vb + (c * 8 + 4) * 72);   // {b01, b11}
            #pragma unroll
            for (int f = 0; f < 2; f++) {
                uint4 aa = f ? a1 : a0;
                asm volatile(
                    "mma.sync.aligned.m16n8k16.row.col.f32.f16.f16.f32 "
                    "{%0,%1,%2,%3}, {%4,%5,%6,%7}, {%8,%9}, {%0,%1,%2,%3};"
                    : "+f"(M[f][0][0]), "+f"(M[f][0][1]), "+f"(M[f][0][2]), "+f"(M[f][0][3])
                    : "r"(aa.x), "r"(aa.y), "r"(aa.z), "r"(aa.w), "r"(B0.x), "r"(B1.x));
                asm volatile(
                    "mma.sync.aligned.m16n8k16.row.col.f32.f16.f16.f32 "
                    "{%0,%1,%2,%3}, {%4,%5,%6,%7}, {%8,%9}, {%0,%1,%2,%3};"
                    : "+f"(M[f][1][0]), "+f"(M[f][1][1]), "+f"(M[f][1][2]), "+f"(M[f][1][3])
                    : "r"(aa.x), "r"(aa.y), "r"(aa.z), "r"(aa.w), "r"(B0.y), "r"(B1.y));
            }
        }
        // Fold M into Y with A^T coeffs: At0 = [1,1,1,0], At1 = [0,1,-1,-1]
        int xi = p >> 2, eta = p & 3;
        float cx0 = (xi == 3) ? 0.f : 1.f;
        float cx1 = (xi == 0) ? 0.f : ((xi == 1) ? 1.f : -1.f);
        float cy0 = (eta == 3) ? 0.f : 1.f;
        float cy1 = (eta == 0) ? 0.f : ((eta == 1) ? 1.f : -1.f);
        float c00 = cx0 * cy0, c01 = cx0 * cy1, c10 = cx1 * cy0, c11 = cx1 * cy1;
        #pragma unroll
        for (int f = 0; f < 2; f++)
            #pragma unroll
            for (int nf = 0; nf < 2; nf++)
                #pragma unroll
                for (int j = 0; j < 4; j++) {
                    float m = M[f][nf][j];
                    Y[f][nf][j][0] = fmaf(c00, m, Y[f][nf][j][0]);
                    Y[f][nf][j][1] = fmaf(c01, m, Y[f][nf][j][1]);
                    Y[f][nf][j][2] = fmaf(c10, m, Y[f][nf][j][2]);
                    Y[f][nf][j][3] = fmaf(c11, m, Y[f][nf][j][3]);
                }
    }

    // Fused minGRU epilogue -> packed half2 (a, b), uint2 per 2x1 px pair
    const float bg0 = __ldg(bias + og * 16 + g4),      bg1 = __ldg(bias + og * 16 + g4 + 8);
    const float bh0 = __ldg(bias + 64 + og * 16 + g4), bh1 = __ldg(bias + 64 + og * 16 + g4 + 8);
    #pragma unroll
    for (int nf = 0; nf < 2; nf++)
        #pragma unroll
        for (int j = 0; j < 4; j++) {
            int oc = og * 16 + g4 + ((j >> 1) * 8);
            int tc = nf * 8 + 2 * tig + (j & 1);
            float bg = (j >> 1) ? bg1 : bg0, bh = (j >> 1) ? bh1 : bh0;
            #pragma unroll
            for (int di = 0; di < 2; di++) {
                int row = r0 + 2 * tg + di;
                float g0 = Y[0][nf][j][di * 2 + 0] + bg;
                float g1 = Y[0][nf][j][di * 2 + 1] + bg;
                float h0 = Y[1][nf][j][di * 2 + 0] + bh;
                float h1 = Y[1][nf][j][di * 2 + 1] + bh;
                float z0 = sigm(g0), z1 = sigm(g1);
                float q0 = (h0 >= 0.f) ? h0 + 0.5f : sigm(h0);
                float q1 = (h1 >= 0.f) ? h1 + 0.5f : sigm(h1);
                uint2 pk;
                pk.x = pkh2(1.f - z0, z0 * q0);
                pk.y = pkh2(1.f - z1, z1 * q1);
                *(uint2*)(ABout + ((n * 64 + oc) << 10) + (row << 5) + 2 * tc) = pk;
            }
        }
}

// Scan layer 1 (R12-verified): one thread per channel PAIR; reads packed (a,b);
// writes packed half2 O1 + fp32 h1.
__global__ void __launch_bounds__(256)
scan1_k(const uint32_t* __restrict__ AB,
        uint32_t* __restrict__ o1p, float* __restrict__ h1)
{
    int idx = blockIdx.x * 256 + threadIdx.x;       // 131072
    int b = idx >> 15, rem = idx & 32767;
    int icp = rem >> 10, px = rem & 1023;
    size_t base = (size_t)b * 64 * 65536 + icp * 2048 + px;
    float h0 = 0.5f, h1v = 0.5f;
    #pragma unroll 8
    for (int t = 0; t < 64; t++) {
        size_t off = base + (size_t)t * 65536;
        uint32_t p0 = AB[off], p1 = AB[off + 1024];
        float2 c0 = __half22float2(*(__half2*)&p0);
        float2 c1 = __half22float2(*(__half2*)&p1);
        h0  = fmaf(c0.x, h0,  c0.y);
        h1v = fmaf(c1.x, h1v, c1.y);
        o1p[(size_t)(b * 64 + t) * 32768 + rem] = pkh2(h0, h1v);
    }
    h1[b * 65536 + icp * 2048 + px]        = h0;
    h1[b * 65536 + icp * 2048 + 1024 + px] = h1v;
}

// Scan layer 2 (R12-verified): reads packed (a,b); fp32 out, float2 stores.
__global__ void __launch_bounds__(256)
scan2_k(const uint32_t* __restrict__ AB,
        float* __restrict__ out, float* __restrict__ h2)
{
    int idx = blockIdx.x * 256 + threadIdx.x;       // 131072 px-pair lanes
    int b = idx >> 15, j = idx & 32767;
    size_t base = (size_t)b * 64 * 32768 + j;
    const uint2* AB2 = (const uint2*)AB;
    float2* o2 = (float2*)out;
    float h0 = 0.5f, h1v = 0.5f;
    #pragma unroll 8
    for (int t = 0; t < 64; t++) {
        size_t off = base + (size_t)t * 32768;
        uint2 p = AB2[off];
        float2 c0 = __half22float2(*(__half2*)&p.x);
        float2 c1 = __half22float2(*(__half2*)&p.y);
        h0  = fmaf(c0.x, h0,  c0.y);
        h1v = fmaf(c1.x, h1v, c1.y);
        o2[off] = make_float2(h0, h1v);
    }
    ((float2*)h2)[b * 32768 + j] = make_float2(h0, h1v);
}

extern "C" void kernel_launch(void* const* d_in, const int* in_sizes, int n_in,
                              void* d_out, int out_size) {
    const float* x  = (const float*)d_in[0];
    const float* w1 = (const float*)d_in[1];
    const float* b1 = (const float*)d_in[2];
    const float* w2 = (const float*)d_in[3];
    const float* b2 = (const float*)d_in[4];
    float* out = (float*)d_out;

    float *pH;
    uint32_t *pAB, *pO1p, *pU1, *pU2;
    cudaGetSymbolAddress((void**)&pAB,  g_AB);
    cudaGetSymbolAddress((void**)&pO1p, g_O1p);
    cudaGetSymbolAddress((void**)&pH,   g_hdump);
    cudaGetSymbolAddress((void**)&pU1,  g_U1);
    cudaGetSymbolAddress((void**)&pU2,  g_U2);

    const int SMEM1 = (16 * 360 + 16 * 16 * 72) * 4;   //  96768
    const int SMEM2 = (32 * 360 + 16 * 32 * 72) * 4;   // 193536
    cudaFuncSetAttribute(conv_wino<32,false>, cudaFuncAttributeMaxDynamicSharedMemorySize, SMEM1);
    cudaFuncSetAttribute(conv_wino<64,true>,  cudaFuncAttributeMaxDynamicSharedMemorySize, SMEM2);

    bool full = (out_size >= TOT + 8 * PLANE);
    float* h1 = full ? (out + TOT)             : pH;
    float* h2 = full ? (out + TOT + 4 * PLANE) : pH;

    pack_both<<<384, 256>>>(w1, pU1, w2, pU2);
    conv_wino<32,false><<<1024, 512, SMEM1>>>(x, pU1, b1, pAB);
    scan1_k<<<512, 256>>>(pAB, pO1p, h1);
    conv_wino<64,true><<<1024, 512, SMEM2>>>(pO1p, pU2, b2, pAB);
    scan2_k<<<512, 256>>>(pAB, out, h2);
}

// round 16
// speedup vs baseline: 1.1085x; 1.0208x over previous
#include <cuda_runtime.h>
#include <cuda_fp16.h>
#include <math.h>
#include <stdint.h>

#define NIMG  256
#define PLANE 65536
#define TOT   16777216

// Scratch (__device__ globals per allocation rules)
__device__ uint32_t g_AB[TOT];         // packed half2 (a, b) per element
__device__ uint32_t g_O1p[TOT/2];      // layer1 output, channel-pair half2 packed
__device__ float    g_hdump[4*PLANE];
__device__ uint32_t g_U1[32768];       // Winograd-transformed weights, fragment order
__device__ uint32_t g_U2[65536];

__device__ __forceinline__ float sigm(float x) { return 1.f/(1.f+__expf(-x)); }
__device__ __forceinline__ uint32_t pkh2(float a, float b) {
    __half2 h = __floats2half2_rn(a, b);
    return *(uint32_t*)&h;
}

// Pack Winograd-transformed weights U = G w G^T (4x4 per oc,ic) into mma-fragment
// order: slab = (p*4 + ocgrp)*2 + f ; per slab KC chunks of 128 u32 (lane*4 + q).
template<int IC>
__device__ __forceinline__ void pack_u_body(const float* __restrict__ w,
                                            uint32_t* __restrict__ dst, int idx) {
    constexpr int KC = IC / 16;
    if (idx >= 128 * KC * 128) return;
    int slab = idx / (KC * 128);
    int rem  = idx - slab * (KC * 128);
    int c = rem >> 7, rem2 = rem & 127;
    int lane = rem2 >> 2, q = rem2 & 3;
    int f  = slab & 1;
    int og = (slab >> 1) & 3;
    int p  = slab >> 3;
    int xi = p >> 2, eta = p & 3;
    int oc = f * 64 + og * 16 + (lane >> 2) + (q & 1) * 8;
    int k  = c * 16 + 2 * (lane & 3) + (q >> 1) * 8;
    const float G[4][3] = {{1,0,0},{0.5f,0.5f,0.5f},{0.5f,-0.5f,0.5f},{0,0,1}};
    float u[2];
    #pragma unroll
    for (int t = 0; t < 2; t++) {
        const float* wp = w + (oc * IC + k + t) * 9;
        float a = 0.f;
        for (int i = 0; i < 3; i++)
            for (int j = 0; j < 3; j++)
                a += G[xi][i] * G[eta][j] * wp[i * 3 + j];
        u[t] = a;
    }
    dst[idx] = pkh2(u[0], u[1]);
}

// Single launch packs both layers: blocks [0,128) -> U1 (IC=32), [128,384) -> U2.
__global__ void __launch_bounds__(256)
pack_both(const float* __restrict__ w1, uint32_t* __restrict__ d1,
          const float* __restrict__ w2, uint32_t* __restrict__ d2) {
    int bx = blockIdx.x;
    if (bx < 128) pack_u_body<32>(w1, d1, bx * 256 + threadIdx.x);
    else          pack_u_body<64>(w2, d2, (bx - 128) * 256 + threadIdx.x);
}

// Winograd F(2x2,3x3) conv + fused minGRU epilogue. (R8/R12 configuration, verbatim —
// the measured optimum across 5 attempted restructurings.)
// Grid 1024 = 256 images x 4 bands (8 rows = 4 tile-rows). 512 threads = 16 warps.
// Warp (og, tg): 32 oc (16 gate og*16.. + paired hidden +64) x tile-row tg (16 tiles).
// Loop 16 transform points: GEMM K=IC from U (gmem, frag-packed) x V (smem),
// fold M into Y via A^T coeffs {0,+-1}. V pitch 72: LDS bank 8*(l%4)+l/4, conflict-free.
template<int IC, bool PIN>
__global__ void __launch_bounds__(512, 1)
conv_wino(const void* __restrict__ xin_, const uint32_t* __restrict__ Upk,
          const float* __restrict__ bias, uint32_t* __restrict__ ABout)
{
    extern __shared__ uint32_t sm[];
    constexpr int KC  = IC / 16;
    constexpr int ICP = IC / 2;
    constexpr int VP  = ICP * 72;          // u32 per transform point
    uint32_t* tile2 = sm;                  // [ICP][10 rows][36 cols] half2
    uint32_t* V     = sm + ICP * 360;      // [16 points][ICP kpairs][72 (64 tiles)]

    const int tid = threadIdx.x;
    const int wv = tid >> 5, lane = tid & 31;
    const int g4 = lane >> 2, tig = lane & 3;
    const int og = wv & 3, tg = wv >> 2;
    const int blk = blockIdx.x, band = blk & 3, n = blk >> 2, r0 = band * 8;

    // Stage padded input: rows r0-1..r0+8 (10), cols -1..33 (36), channel-pair half2
    for (int idx = tid; idx < ICP * 360; idx += 512) {
        int icp = idx / 360, rem = idx - icp * 360, r = rem / 36, c = rem - r * 36;
        int gr = r0 + r - 1, gc = c - 1;
        uint32_t v = 0;
        if ((unsigned)gr < 32u && (unsigned)gc < 32u) {
            if (PIN) {
                v = ((const uint32_t*)xin_)[n * 32768 + icp * 1024 + (gr << 5) + gc];
            } else {
                const float* x = (const float*)xin_;
                int base = ((n * IC + 2 * icp) << 10) + (gr << 5) + gc;
                v = pkh2(x[base], x[base + 1024]);
            }
        }
        tile2[idx] = v;
    }
    __syncthreads();

    // Input transform: per (icpair, tile): V = B^T d B (on half2 = 2 channels at once)
    for (int u = tid; u < ICP * 64; u += 512) {
        int icp = u >> 6, rem = u & 63, tr = rem >> 4, tc = rem & 15;
        const uint32_t* dp = tile2 + icp * 360 + (2 * tr) * 36 + 2 * tc;
        float2 d[4][4];
        #pragma unroll
        for (int i = 0; i < 4; i++)
            #pragma unroll
            for (int j = 0; j < 4; j++) {
                uint32_t raw = dp[i * 36 + j];
                d[i][j] = __half22float2(*(__half2*)&raw);
            }
        float2 t[4][4];
        #pragma unroll
        for (int j = 0; j < 4; j++) {
            t[0][j] = make_float2(d[0][j].x - d[2][j].x, d[0][j].y - d[2][j].y);
            t[1][j] = make_float2(d[1][j].x + d[2][j].x, d[1][j].y + d[2][j].y);
            t[2][j] = make_float2(d[2][j].x - d[1][j].x, d[2][j].y - d[1][j].y);
            t[3][j] = make_float2(d[1][j].x - d[3][j].x, d[1][j].y - d[3][j].y);
        }
        uint32_t* vp = V + icp * 72 + tr * 16 + tc;
        #pragma unroll
        for (int xi = 0; xi < 4; xi++) {
            float2 v0 = make_float2(t[xi][0].x - t[xi][2].x, t[xi][0].y - t[xi][2].y);
            float2 v1 = make_float2(t[xi][1].x + t[xi][2].x, t[xi][1].y + t[xi][2].y);
            float2 v2 = make_float2(t[xi][2].x - t[xi][1].x, t[xi][2].y - t[xi][1].y);
            float2 v3 = make_float2(t[xi][1].x - t[xi][3].x, t[xi][1].y - t[xi][3].y);
            vp[(xi * 4 + 0) * VP] = pkh2(v0.x, v0.y);
            vp[(xi * 4 + 1) * VP] = pkh2(v1.x, v1.y);
            vp[(xi * 4 + 2) * VP] = pkh2(v2.x, v2.y);
            vp[(xi * 4 + 3) * VP] = pkh2(v3.x, v3.y);
        }
    }
    __syncthreads();

    float Y[2][2][4][4];   // [f gate/hid][nf][acc j][di*2+dj]
    #pragma unroll
    for (int f = 0; f < 2; f++)
        #pragma unroll
        for (int nf = 0; nf < 2; nf++)
            #pragma unroll
            for (int j = 0; j < 4; j++)
                #pragma unroll
                for (int e = 0; e < 4; e++) Y[f][nf][j][e] = 0.f;

    for (int p = 0; p < 16; p++) {
        float M[2][2][4];
        #pragma unroll
        for (int f = 0; f < 2; f++)
            #pragma unroll
            for (int nf = 0; nf < 2; nf++)
                #pragma unroll
                for (int j = 0; j < 4; j++) M[f][nf][j] = 0.f;

        const uint32_t* Ub = Upk + (size_t)((p * 4 + og) * 2) * KC * 128;
        const uint32_t* Vb = V + p * VP + tig * 72 + tg * 16 + g4;
        #pragma unroll
        for (int c = 0; c < KC; c++) {
            uint4 a0 = *(const uint4*)(Ub + c * 128 + lane * 4);
            uint4 a1 = *(const uint4*)(Ub + KC * 128 + c * 128 + lane * 4);
            uint32_t b00 = Vb[(c * 8) * 72];
            uint32_t b01 = Vb[(c * 8 + 4) * 72];
            uint32_t b10 = Vb[(c * 8) * 72 + 8];
            uint32_t b11 = Vb[(c * 8 + 4) * 72 + 8];
            #pragma unroll
            for (int f = 0; f < 2; f++) {
                uint4 aa = f ? a1 : a0;
                asm volatile(
                    "mma.sync.aligned.m16n8k16.row.col.f32.f16.f16.f32 "
                    "{%0,%1,%2,%3}, {%4,%5,%6,%7}, {%8,%9}, {%0,%1,%2,%3};"
                    : "+f"(M[f][0][0]), "+f"(M[f][0][1]), "+f"(M[f][0][2]), "+f"(M[f][0][3])
                    : "r"(aa.x), "r"(aa.y), "r"(aa.z), "r"(aa.w), "r"(b00), "r"(b01));
                asm volatile(
                    "mma.sync.aligned.m16n8k16.row.col.f32.f16.f16.f32 "
                    "{%0,%1,%2,%3}, {%4,%5,%6,%7}, {%8,%9}, {%0,%1,%2,%3};"
                    : "+f"(M[f][1][0]), "+f"(M[f][1][1]), "+f"(M[f][1][2]), "+f"(M[f][1][3])
                    : "r"(aa.x), "r"(aa.y), "r"(aa.z), "r"(aa.w), "r"(b10), "r"(b11));
            }
        }
        // Fold M into Y with A^T coeffs: At0 = [1,1,1,0], At1 = [0,1,-1,-1]
        int xi = p >> 2, eta = p & 3;
        float cx0 = (xi == 3) ? 0.f : 1.f;
        float cx1 = (xi == 0) ? 0.f : ((xi == 1) ? 1.f : -1.f);
        float cy0 = (eta == 3) ? 0.f : 1.f;
        float cy1 = (eta == 0) ? 0.f : ((eta == 1) ? 1.f : -1.f);
        float c00 = cx0 * cy0, c01 = cx0 * cy1, c10 = cx1 * cy0, c11 = cx1 * cy1;
        #pragma unroll
        for (int f = 0; f < 2; f++)
            #pragma unroll
            for (int nf = 0; nf < 2; nf++)
                #pragma unroll
                for (int j = 0; j < 4; j++) {
                    float m = M[f][nf][j];
                    Y[f][nf][j][0] = fmaf(c00, m, Y[f][nf][j][0]);
                    Y[f][nf][j][1] = fmaf(c01, m, Y[f][nf][j][1]);
                    Y[f][nf][j][2] = fmaf(c10, m, Y[f][nf][j][2]);
                    Y[f][nf][j][3] = fmaf(c11, m, Y[f][nf][j][3]);
                }
    }

    // Fused minGRU epilogue -> packed half2 (a, b), uint2 per 2x1 px pair
    const float bg0 = __ldg(bias + og * 16 + g4),      bg1 = __ldg(bias + og * 16 + g4 + 8);
    const float bh0 = __ldg(bias + 64 + og * 16 + g4), bh1 = __ldg(bias + 64 + og * 16 + g4 + 8);
    #pragma unroll
    for (int nf = 0; nf < 2; nf++)
        #pragma unroll
        for (int j = 0; j < 4; j++) {
            int oc = og * 16 + g4 + ((j >> 1) * 8);
            int tc = nf * 8 + 2 * tig + (j & 1);
            float bg = (j >> 1) ? bg1 : bg0, bh = (j >> 1) ? bh1 : bh0;
            #pragma unroll
            for (int di = 0; di < 2; di++) {
                int row = r0 + 2 * tg + di;
                float g0 = Y[0][nf][j][di * 2 + 0] + bg;
                float g1 = Y[0][nf][j][di * 2 + 1] + bg;
                float h0 = Y[1][nf][j][di * 2 + 0] + bh;
                float h1 = Y[1][nf][j][di * 2 + 1] + bh;
                float z0 = sigm(g0), z1 = sigm(g1);
                float q0 = (h0 >= 0.f) ? h0 + 0.5f : sigm(h0);
                float q1 = (h1 >= 0.f) ? h1 + 0.5f : sigm(h1);
                uint2 pk;
                pk.x = pkh2(1.f - z0, z0 * q0);
                pk.y = pkh2(1.f - z1, z1 * q1);
                *(uint2*)(ABout + ((n * 64 + oc) << 10) + (row << 5) + 2 * tc) = pk;
            }
        }
}

// Scan layer 1 (R12-verified): one thread per channel PAIR; reads packed (a,b);
// writes packed half2 O1 + fp32 h1.
__global__ void __launch_bounds__(256)
scan1_k(const uint32_t* __restrict__ AB,
        uint32_t* __restrict__ o1p, float* __restrict__ h1)
{
    int idx = blockIdx.x * 256 + threadIdx.x;       // 131072
    int b = idx >> 15, rem = idx & 32767;
    int icp = rem >> 10, px = rem & 1023;
    size_t base = (size_t)b * 64 * 65536 + icp * 2048 + px;
    float h0 = 0.5f, h1v = 0.5f;
    #pragma unroll 8
    for (int t = 0; t < 64; t++) {
        size_t off = base + (size_t)t * 65536;
        uint32_t p0 = AB[off], p1 = AB[off + 1024];
        float2 c0 = __half22float2(*(__half2*)&p0);
        float2 c1 = __half22float2(*(__half2*)&p1);
        h0  = fmaf(c0.x, h0,  c0.y);
        h1v = fmaf(c1.x, h1v, c1.y);
        o1p[(size_t)(b * 64 + t) * 32768 + rem] = pkh2(h0, h1v);
    }
    h1[b * 65536 + icp * 2048 + px]        = h0;
    h1[b * 65536 + icp * 2048 + 1024 + px] = h1v;
}

// Scan layer 2 (R12-verified): reads packed (a,b); fp32 out, float2 stores.
__global__ void __launch_bounds__(256)
scan2_k(const uint32_t* __restrict__ AB,
        float* __restrict__ out, float* __restrict__ h2)
{
    int idx = blockIdx.x * 256 + threadIdx.x;       // 131072 px-pair lanes
    int b = idx >> 15, j = idx & 32767;
    size_t base = (size_t)b * 64 * 32768 + j;
    const uint2* AB2 = (const uint2*)AB;
    float2* o2 = (float2*)out;
    float h0 = 0.5f, h1v = 0.5f;
    #pragma unroll 8
    for (int t = 0; t < 64; t++) {
        size_t off = base + (size_t)t * 32768;
        uint2 p = AB2[off];
        float2 c0 = __half22float2(*(__half2*)&p.x);
        float2 c1 = __half22float2(*(__half2*)&p.y);
        h0  = fmaf(c0.x, h0,  c0.y);
        h1v = fmaf(c1.x, h1v, c1.y);
        o2[off] = make_float2(h0, h1v);
    }
    ((float2*)h2)[b * 32768 + j] = make_float2(h0, h1v);
}

extern "C" void kernel_launch(void* const* d_in, const int* in_sizes, int n_in,
                              void* d_out, int out_size) {
    const float* x  = (const float*)d_in[0];
    const float* w1 = (const float*)d_in[1];
    const float* b1 = (const float*)d_in[2];
    const float* w2 = (const float*)d_in[3];
    const float* b2 = (const float*)d_in[4];
    float* out = (float*)d_out;

    float *pH;
    uint32_t *pAB, *pO1p, *pU1, *pU2;
    cudaGetSymbolAddress((void**)&pAB,  g_AB);
    cudaGetSymbolAddress((void**)&pO1p, g_O1p);
    cudaGetSymbolAddress((void**)&pH,   g_hdump);
    cudaGetSymbolAddress((void**)&pU1,  g_U1);
    cudaGetSymbolAddress((void**)&pU2,  g_U2);

    const int SMEM1 = (16 * 360 + 16 * 16 * 72) * 4;   //  96768
    const int SMEM2 = (32 * 360 + 16 * 32 * 72) * 4;   // 193536
    cudaFuncSetAttribute(conv_wino<32,false>, cudaFuncAttributeMaxDynamicSharedMemorySize, SMEM1);
    cudaFuncSetAttribute(conv_wino<64,true>,  cudaFuncAttributeMaxDynamicSharedMemorySize, SMEM2);

    bool full = (out_size >= TOT + 8 * PLANE);
    float* h1 = full ? (out + TOT)             : pH;
    float* h2 = full ? (out + TOT + 4 * PLANE) : pH;

    pack_both<<<384, 256>>>(w1, pU1, w2, pU2);
    conv_wino<32,false><<<1024, 512, SMEM1>>>(x, pU1, b1, pAB);
    scan1_k<<<512, 256>>>(pAB, pO1p, h1);
    conv_wino<64,true><<<1024, 512, SMEM2>>>(pO1p, pU2, b2, pAB);
    scan2_k<<<512, 256>>>(pAB, out, h2);
}

// round 17
// speedup vs baseline: 1.2043x; 1.0865x over previous
#include <cuda_runtime.h>
#include <cuda_fp16.h>
#include <math.h>
#include <stdint.h>

#define NIMG  256
#define PLANE 65536
#define TOT   16777216

// Scratch (__device__ globals per allocation rules)
__device__ uint32_t g_AB[TOT];         // packed half2 (a, b) per element
__device__ uint32_t g_O1p[TOT/2];      // layer1 output, channel-pair half2 packed
__device__ float    g_hdump[4*PLANE];
__device__ uint32_t g_U1[32768];       // Winograd-transformed weights, fragment order
__device__ uint32_t g_U2[65536];

// Fast sigmoid: MUFU.RCP path (rel err ~2^-21, far below the 3.6e-4 noise floor)
__device__ __forceinline__ float sigm(float x) {
    return __fdividef(1.f, 1.f + __expf(-x));
}
__device__ __forceinline__ uint32_t pkh2(float a, float b) {
    __half2 h = __floats2half2_rn(a, b);
    return *(uint32_t*)&h;
}

// Pack Winograd-transformed weights U = G w G^T (4x4 per oc,ic) into mma-fragment
// order: slab = (p*4 + ocgrp)*2 + f ; per slab KC chunks of 128 u32 (lane*4 + q).
template<int IC>
__device__ __forceinline__ void pack_u_body(const float* __restrict__ w,
                                            uint32_t* __restrict__ dst, int idx) {
    constexpr int KC = IC / 16;
    if (idx >= 128 * KC * 128) return;
    int slab = idx / (KC * 128);
    int rem  = idx - slab * (KC * 128);
    int c = rem >> 7, rem2 = rem & 127;
    int lane = rem2 >> 2, q = rem2 & 3;
    int f  = slab & 1;
    int og = (slab >> 1) & 3;
    int p  = slab >> 3;
    int xi = p >> 2, eta = p & 3;
    int oc = f * 64 + og * 16 + (lane >> 2) + (q & 1) * 8;
    int k  = c * 16 + 2 * (lane & 3) + (q >> 1) * 8;
    const float G[4][3] = {{1,0,0},{0.5f,0.5f,0.5f},{0.5f,-0.5f,0.5f},{0,0,1}};
    float u[2];
    #pragma unroll
    for (int t = 0; t < 2; t++) {
        const float* wp = w + (oc * IC + k + t) * 9;
        float a = 0.f;
        for (int i = 0; i < 3; i++)
            for (int j = 0; j < 3; j++)
                a += G[xi][i] * G[eta][j] * wp[i * 3 + j];
        u[t] = a;
    }
    dst[idx] = pkh2(u[0], u[1]);
}

// Single launch packs both layers: blocks [0,128) -> U1 (IC=32), [128,384) -> U2.
__global__ void __launch_bounds__(256)
pack_both(const float* __restrict__ w1, uint32_t* __restrict__ d1,
          const float* __restrict__ w2, uint32_t* __restrict__ d2) {
    int bx = blockIdx.x;
    if (bx < 128) pack_u_body<32>(w1, d1, bx * 256 + threadIdx.x);
    else          pack_u_body<64>(w2, d2, (bx - 128) * 256 + threadIdx.x);
}

// Winograd F(2x2,3x3) conv + fused minGRU epilogue. (R8/R12/R16 configuration —
// the measured optimum across 5 attempted restructurings; only sigm() fast-pathed.)
// Grid 1024 = 256 images x 4 bands (8 rows = 4 tile-rows). 512 threads = 16 warps.
// Warp (og, tg): 32 oc (16 gate og*16.. + paired hidden +64) x tile-row tg (16 tiles).
// Loop 16 transform points: GEMM K=IC from U (gmem, frag-packed) x V (smem),
// fold M into Y via A^T coeffs {0,+-1}. V pitch 72: LDS bank 8*(l%4)+l/4, conflict-free.
template<int IC, bool PIN>
__global__ void __launch_bounds__(512, 1)
conv_wino(const void* __restrict__ xin_, const uint32_t* __restrict__ Upk,
          const float* __restrict__ bias, uint32_t* __restrict__ ABout)
{
    extern __shared__ uint32_t sm[];
    constexpr int KC  = IC / 16;
    constexpr int ICP = IC / 2;
    constexpr int VP  = ICP * 72;          // u32 per transform point
    uint32_t* tile2 = sm;                  // [ICP][10 rows][36 cols] half2
    uint32_t* V     = sm + ICP * 360;      // [16 points][ICP kpairs][72 (64 tiles)]

    const int tid = threadIdx.x;
    const int wv = tid >> 5, lane = tid & 31;
    const int g4 = lane >> 2, tig = lane & 3;
    const int og = wv & 3, tg = wv >> 2;
    const int blk = blockIdx.x, band = blk & 3, n = blk >> 2, r0 = band * 8;

    // Stage padded input: rows r0-1..r0+8 (10), cols -1..33 (36), channel-pair half2
    for (int idx = tid; idx < ICP * 360; idx += 512) {
        int icp = idx / 360, rem = idx - icp * 360, r = rem / 36, c = rem - r * 36;
        int gr = r0 + r - 1, gc = c - 1;
        uint32_t v = 0;
        if ((unsigned)gr < 32u && (unsigned)gc < 32u) {
            if (PIN) {
                v = ((const uint32_t*)xin_)[n * 32768 + icp * 1024 + (gr << 5) + gc];
            } else {
                const float* x = (const float*)xin_;
                int base = ((n * IC + 2 * icp) << 10) + (gr << 5) + gc;
                v = pkh2(x[base], x[base + 1024]);
            }
        }
        tile2[idx] = v;
    }
    __syncthreads();

    // Input transform: per (icpair, tile): V = B^T d B (on half2 = 2 channels at once)
    for (int u = tid; u < ICP * 64; u += 512) {
        int icp = u >> 6, rem = u & 63, tr = rem >> 4, tc = rem & 15;
        const uint32_t* dp = tile2 + icp * 360 + (2 * tr) * 36 + 2 * tc;
        float2 d[4][4];
        #pragma unroll
        for (int i = 0; i < 4; i++)
            #pragma unroll
            for (int j = 0; j < 4; j++) {
                uint32_t raw = dp[i * 36 + j];
                d[i][j] = __half22float2(*(__half2*)&raw);
            }
        float2 t[4][4];
        #pragma unroll
        for (int j = 0; j < 4; j++) {
            t[0][j] = make_float2(d[0][j].x - d[2][j].x, d[0][j].y - d[2][j].y);
            t[1][j] = make_float2(d[1][j].x + d[2][j].x, d[1][j].y + d[2][j].y);
            t[2][j] = make_float2(d[2][j].x - d[1][j].x, d[2][j].y - d[1][j].y);
            t[3][j] = make_float2(d[1][j].x - d[3][j].x, d[1][j].y - d[3][j].y);
        }
        uint32_t* vp = V + icp * 72 + tr * 16 + tc;
        #pragma unroll
        for (int xi = 0; xi < 4; xi++) {
            float2 v0 = make_float2(t[xi][0].x - t[xi][2].x, t[xi][0].y - t[xi][2].y);
            float2 v1 = make_float2(t[xi][1].x + t[xi][2].x, t[xi][1].y + t[xi][2].y);
            float2 v2 = make_float2(t[xi][2].x - t[xi][1].x, t[xi][2].y - t[xi][1].y);
            float2 v3 = make_float2(t[xi][1].x - t[xi][3].x, t[xi][1].y - t[xi][3].y);
            vp[(xi * 4 + 0) * VP] = pkh2(v0.x, v0.y);
            vp[(xi * 4 + 1) * VP] = pkh2(v1.x, v1.y);
            vp[(xi * 4 + 2) * VP] = pkh2(v2.x, v2.y);
            vp[(xi * 4 + 3) * VP] = pkh2(v3.x, v3.y);
        }
    }
    __syncthreads();

    float Y[2][2][4][4];   // [f gate/hid][nf][acc j][di*2+dj]
    #pragma unroll
    for (int f = 0; f < 2; f++)
        #pragma unroll
        for (int nf = 0; nf < 2; nf++)
            #pragma unroll
            for (int j = 0; j < 4; j++)
                #pragma unroll
                for (int e = 0; e < 4; e++) Y[f][nf][j][e] = 0.f;

    for (int p = 0; p < 16; p++) {
        float M[2][2][4];
        #pragma unroll
        for (int f = 0; f < 2; f++)
            #pragma unroll
            for (int nf = 0; nf < 2; nf++)
                #pragma unroll
                for (int j = 0; j < 4; j++) M[f][nf][j] = 0.f;

        const uint32_t* Ub = Upk + (size_t)((p * 4 + og) * 2) * KC * 128;
        const uint32_t* Vb = V + p * VP + tig * 72 + tg * 16 + g4;
        #pragma unroll
        for (int c = 0; c < KC; c++) {
            uint4 a0 = *(const uint4*)(Ub + c * 128 + lane * 4);
            uint4 a1 = *(const uint4*)(Ub + KC * 128 + c * 128 + lane * 4);
            uint32_t b00 = Vb[(c * 8) * 72];
            uint32_t b01 = Vb[(c * 8 + 4) * 72];
            uint32_t b10 = Vb[(c * 8) * 72 + 8];
            uint32_t b11 = Vb[(c * 8 + 4) * 72 + 8];
            #pragma unroll
            for (int f = 0; f < 2; f++) {
                uint4 aa = f ? a1 : a0;
                asm volatile(
                    "mma.sync.aligned.m16n8k16.row.col.f32.f16.f16.f32 "
                    "{%0,%1,%2,%3}, {%4,%5,%6,%7}, {%8,%9}, {%0,%1,%2,%3};"
                    : "+f"(M[f][0][0]), "+f"(M[f][0][1]), "+f"(M[f][0][2]), "+f"(M[f][0][3])
                    : "r"(aa.x), "r"(aa.y), "r"(aa.z), "r"(aa.w), "r"(b00), "r"(b01));
                asm volatile(
                    "mma.sync.aligned.m16n8k16.row.col.f32.f16.f16.f32 "
                    "{%0,%1,%2,%3}, {%4,%5,%6,%7}, {%8,%9}, {%0,%1,%2,%3};"
                    : "+f"(M[f][1][0]), "+f"(M[f][1][1]), "+f"(M[f][1][2]), "+f"(M[f][1][3])
                    : "r"(aa.x), "r"(aa.y), "r"(aa.z), "r"(aa.w), "r"(b10), "r"(b11));
            }
        }
        // Fold M into Y with A^T coeffs: At0 = [1,1,1,0], At1 = [0,1,-1,-1]
        int xi = p >> 2, eta = p & 3;
        float cx0 = (xi == 3) ? 0.f : 1.f;
        float cx1 = (xi == 0) ? 0.f : ((xi == 1) ? 1.f : -1.f);
        float cy0 = (eta == 3) ? 0.f : 1.f;
        float cy1 = (eta == 0) ? 0.f : ((eta == 1) ? 1.f : -1.f);
        float c00 = cx0 * cy0, c01 = cx0 * cy1, c10 = cx1 * cy0, c11 = cx1 * cy1;
        #pragma unroll
        for (int f = 0; f < 2; f++)
            #pragma unroll
            for (int nf = 0; nf < 2; nf++)
                #pragma unroll
                for (int j = 0; j < 4; j++) {
                    float m = M[f][nf][j];
                    Y[f][nf][j][0] = fmaf(c00, m, Y[f][nf][j][0]);
                    Y[f][nf][j][1] = fmaf(c01, m, Y[f][nf][j][1]);
                    Y[f][nf][j][2] = fmaf(c10, m, Y[f][nf][j][2]);
                    Y[f][nf][j][3] = fmaf(c11, m, Y[f][nf][j][3]);
                }
    }

    // Fused minGRU epilogue -> packed half2 (a, b), uint2 per 2x1 px pair
    const float bg0 = __ldg(bias + og * 16 + g4),      bg1 = __ldg(bias + og * 16 + g4 + 8);
    const float bh0 = __ldg(bias + 64 + og * 16 + g4), bh1 = __ldg(bias + 64 + og * 16 + g4 + 8);
    #pragma unroll
    for (int nf = 0; nf < 2; nf++)
        #pragma unroll
        for (int j = 0; j < 4; j++) {
            int oc = og * 16 + g4 + ((j >> 1) * 8);
            int tc = nf * 8 + 2 * tig + (j & 1);
            float bg = (j >> 1) ? bg1 : bg0, bh = (j >> 1) ? bh1 : bh0;
            #pragma unroll
            for (int di = 0; di < 2; di++) {
                int row = r0 + 2 * tg + di;
                float g0 = Y[0][nf][j][di * 2 + 0] + bg;
                float g1 = Y[0][nf][j][di * 2 + 1] + bg;
                float h0 = Y[1][nf][j][di * 2 + 0] + bh;
                float h1 = Y[1][nf][j][di * 2 + 1] + bh;
                float z0 = sigm(g0), z1 = sigm(g1);
                float q0 = (h0 >= 0.f) ? h0 + 0.5f : sigm(h0);
                float q1 = (h1 >= 0.f) ? h1 + 0.5f : sigm(h1);
                uint2 pk;
                pk.x = pkh2(1.f - z0, z0 * q0);
                pk.y = pkh2(1.f - z1, z1 * q1);
                *(uint2*)(ABout + ((n * 64 + oc) << 10) + (row << 5) + 2 * tc) = pk;
            }
        }
}

// Scan layer 1 (R12-verified): one thread per channel PAIR; reads packed (a,b);
// writes packed half2 O1 + fp32 h1.
__global__ void __launch_bounds__(256)
scan1_k(const uint32_t* __restrict__ AB,
        uint32_t* __restrict__ o1p, float* __restrict__ h1)
{
    int idx = blockIdx.x * 256 + threadIdx.x;       // 131072
    int b = idx >> 15, rem = idx & 32767;
    int icp = rem >> 10, px = rem & 1023;
    size_t base = (size_t)b * 64 * 65536 + icp * 2048 + px;
    float h0 = 0.5f, h1v = 0.5f;
    #pragma unroll 8
    for (int t = 0; t < 64; t++) {
        size_t off = base + (size_t)t * 65536;
        uint32_t p0 = AB[off], p1 = AB[off + 1024];
        float2 c0 = __half22float2(*(__half2*)&p0);
        float2 c1 = __half22float2(*(__half2*)&p1);
        h0  = fmaf(c0.x, h0,  c0.y);
        h1v = fmaf(c1.x, h1v, c1.y);
        o1p[(size_t)(b * 64 + t) * 32768 + rem] = pkh2(h0, h1v);
    }
    h1[b * 65536 + icp * 2048 + px]        = h0;
    h1[b * 65536 + icp * 2048 + 1024 + px] = h1v;
}

// Scan layer 2 (R12-verified): reads packed (a,b); fp32 out, float2 stores.
__global__ void __launch_bounds__(256)
scan2_k(const uint32_t* __restrict__ AB,
        float* __restrict__ out, float* __restrict__ h2)
{
    int idx = blockIdx.x * 256 + threadIdx.x;       // 131072 px-pair lanes
    int b = idx >> 15, j = idx & 32767;
    size_t base = (size_t)b * 64 * 32768 + j;
    const uint2* AB2 = (const uint2*)AB;
    float2* o2 = (float2*)out;
    float h0 = 0.5f, h1v = 0.5f;
    #pragma unroll 8
    for (int t = 0; t < 64; t++) {
        size_t off = base + (size_t)t * 32768;
        uint2 p = AB2[off];
        float2 c0 = __half22float2(*(__half2*)&p.x);
        float2 c1 = __half22float2(*(__half2*)&p.y);
        h0  = fmaf(c0.x, h0,  c0.y);
        h1v = fmaf(c1.x, h1v, c1.y);
        o2[off] = make_float2(h0, h1v);
    }
    ((float2*)h2)[b * 32768 + j] = make_float2(h0, h1v);
}

extern "C" void kernel_launch(void* const* d_in, const int* in_sizes, int n_in,
                              void* d_out, int out_size) {
    const float* x  = (const float*)d_in[0];
    const float* w1 = (const float*)d_in[1];
    const float* b1 = (const float*)d_in[2];
    const float* w2 = (const float*)d_in[3];
    const float* b2 = (const float*)d_in[4];
    float* out = (float*)d_out;

    float *pH;
    uint32_t *pAB, *pO1p, *pU1, *pU2;
    cudaGetSymbolAddress((void**)&pAB,  g_AB);
    cudaGetSymbolAddress((void**)&pO1p, g_O1p);
    cudaGetSymbolAddress((void**)&pH,   g_hdump);
    cudaGetSymbolAddress((void**)&pU1,  g_U1);
    cudaGetSymbolAddress((void**)&pU2,  g_U2);

    const int SMEM1 = (16 * 360 + 16 * 16 * 72) * 4;   //  96768
    const int SMEM2 = (32 * 360 + 16 * 32 * 72) * 4;   // 193536
    cudaFuncSetAttribute(conv_wino<32,false>, cudaFuncAttributeMaxDynamicSharedMemorySize, SMEM1);
    cudaFuncSetAttribute(conv_wino<64,true>,  cudaFuncAttributeMaxDynamicSharedMemorySize, SMEM2);

    bool full = (out_size >= TOT + 8 * PLANE);
    float* h1 = full ? (out + TOT)             : pH;
    float* h2 = full ? (out + TOT + 4 * PLANE) : pH;

    pack_both<<<384, 256>>>(w1, pU1, w2, pU2);
    conv_wino<32,false><<<1024, 512, SMEM1>>>(x, pU1, b1, pAB);
    scan1_k<<<512, 256>>>(pAB, pO1p, h1);
    conv_wino<64,true><<<1024, 512, SMEM2>>>(pO1p, pU2, b2, pAB);
    scan2_k<<<512, 256>>>(pAB, out, h2);
}